// round 1
// baseline (speedup 1.0000x reference)
#include <cuda_runtime.h>

#define Hh 256
#define Ww 704
#define HW (Hh*Ww)
#define CIMG 256
#define COUTC 131

// Scratch (device globals; no allocation allowed)
__device__ float d_gated[HW];
__device__ float d_spt[HW];
__device__ float d_att[HW];
__device__ float d_v2[9*COUTC];
__device__ float d_u0[9*35];
__device__ float d_u1[9*67];
__device__ float d_wg[9];
__device__ float d_K[9];

// ---------------------------------------------------------------------------
// Fold all conv weights into: v2[9][131], u0[9][35], u1[9][67], wg[9], K[9]
// v2[t][j] = sum_c sp_w[c][t] * rd2_w[c][j]
// u0[t][i] = sum_j v2[t][j] * rd0_w[j][i]      (u1 analogous with rd1_w)
// wg[t]    = sum_c sp_w[c][t]
// K[t]     = sum_j v2[t][j]*(rd0_b[j]+rd1_b[j]) + sum_c sp_w[c][t]*rd2_b[c]
// ---------------------------------------------------------------------------
__global__ void precompute_kernel(const float* __restrict__ sp_w,
                                  const float* __restrict__ rd0_w,
                                  const float* __restrict__ rd1_w,
                                  const float* __restrict__ rd0_b,
                                  const float* __restrict__ rd1_b,
                                  const float* __restrict__ rd2_w,
                                  const float* __restrict__ rd2_b) {
    int tid = threadIdx.x;
    for (int idx = tid; idx < 9*COUTC; idx += blockDim.x) {
        int t = idx / COUTC, j = idx % COUTC;
        float a = 0.f;
        for (int c = 0; c < COUTC; ++c) a += sp_w[c*9 + t] * rd2_w[c*COUTC + j];
        d_v2[idx] = a;
    }
    __syncthreads();
    for (int idx = tid; idx < 9*35; idx += blockDim.x) {
        int t = idx / 35, i = idx % 35;
        float a = 0.f;
        for (int j = 0; j < COUTC; ++j) a += d_v2[t*COUTC + j] * rd0_w[j*35 + i];
        d_u0[idx] = a;
    }
    for (int idx = tid; idx < 9*67; idx += blockDim.x) {
        int t = idx / 67, i = idx % 67;
        float a = 0.f;
        for (int j = 0; j < COUTC; ++j) a += d_v2[t*COUTC + j] * rd1_w[j*67 + i];
        d_u1[idx] = a;
    }
    if (tid < 9) {
        int t = tid;
        float w = 0.f, k = 0.f;
        for (int c = 0; c < COUTC; ++c) {
            w += sp_w[c*9 + t];
            k += d_v2[t*COUTC + c] * (rd0_b[c] + rd1_b[c]) + sp_w[c*9 + t] * rd2_b[c];
        }
        d_wg[t] = w;
        d_K[t]  = k;
    }
}

__global__ void zero_spt_kernel() {
    int i = blockIdx.x * blockDim.x + threadIdx.x;
    if (i < HW) d_spt[i] = 0.f;
}

// gated(p) = rd3_b + sum_c rd3_w[c] * img[c][p]   (float4 over 4 pixels/thread)
__global__ void gated_kernel(const float* __restrict__ img,
                             const float* __restrict__ rd3_w,
                             const float* __restrict__ rd3_b) {
    __shared__ float sw[CIMG];
    for (int i = threadIdx.x; i < CIMG; i += blockDim.x) sw[i] = rd3_w[i];
    __syncthreads();
    int p4 = blockIdx.x * blockDim.x + threadIdx.x;
    if (p4 >= HW/4) return;
    const float4* img4 = (const float4*)img;
    float b = rd3_b[0];
    float4 acc = make_float4(b, b, b, b);
    #pragma unroll 8
    for (int c = 0; c < CIMG; ++c) {
        float w = sw[c];
        float4 x = img4[(size_t)c * (HW/4) + p4];
        acc.x += w * x.x; acc.y += w * x.y; acc.z += w * x.z; acc.w += w * x.w;
    }
    ((float4*)d_gated)[p4] = acc;
}

// One warp per point: coalesced feature-row load, 9 folded dot products,
// butterfly reduce, then lanes 0..8 scatter to the 9 neighbor output pixels.
template<int CF>
__global__ void scatter_kernel(const float* __restrict__ feat,
                               const float* __restrict__ coord,
                               const int* __restrict__ grid, int N) {
    constexpr int L = CF + 3;
    const float* u = (CF == 32) ? d_u0 : (CF == 64) ? d_u1 : d_v2;
    __shared__ float su[9 * L];
    for (int i = threadIdx.x; i < 9 * L; i += blockDim.x) su[i] = u[i];
    __syncthreads();
    int gwarp  = (blockIdx.x * blockDim.x + threadIdx.x) >> 5;
    int lane   = threadIdx.x & 31;
    int nwarps = (gridDim.x * blockDim.x) >> 5;
    for (int n = gwarp; n < N; n += nwarps) {
        float acc[9];
        #pragma unroll
        for (int t = 0; t < 9; ++t) acc[t] = 0.f;
        #pragma unroll
        for (int k = 0; k * 32 < L; ++k) {
            int i = lane + k * 32;
            if (i < L) {
                float pv = (i < CF) ? feat[(size_t)n * CF + i]
                                    : coord[n * 3 + (i - CF)];
                #pragma unroll
                for (int t = 0; t < 9; ++t) acc[t] += su[t * L + i] * pv;
            }
        }
        #pragma unroll
        for (int off = 16; off; off >>= 1) {
            #pragma unroll
            for (int t = 0; t < 9; ++t)
                acc[t] += __shfl_xor_sync(0xffffffffu, acc[t], off);
        }
        if (lane < 9) {
            float myv = 0.f;
            #pragma unroll
            for (int t = 0; t < 9; ++t) if (lane == t) myv = acc[t];
            int x = grid[2 * n], y = grid[2 * n + 1];   // grid stores (col, row)
            int dy = lane / 3, dx = lane % 3;
            int h = y - dy + 1, w = x - dx + 1;
            if (h >= 0 && h < Hh && w >= 0 && w < Ww)
                atomicAdd(&d_spt[h * Ww + w], myv);
        }
    }
}

// att(p) = sigmoid( sp_b + spt(p) + sum_{in-bounds taps} wg_t*gated(nbr) + K_t )
__global__ void att_kernel(const float* __restrict__ sp_b) {
    int p = blockIdx.x * blockDim.x + threadIdx.x;
    if (p >= HW) return;
    int h = p / Ww, w = p % Ww;
    float s = sp_b[0] + d_spt[p];
    #pragma unroll
    for (int t = 0; t < 9; ++t) {
        int y = h + t / 3 - 1, x = w + t % 3 - 1;
        if (y >= 0 && y < Hh && x >= 0 && x < Ww)
            s += d_wg[t] * d_gated[y * Ww + x] + d_K[t];
    }
    d_att[p] = 1.f / (1.f + __expf(-s));
}

// out[c][p] = img[c][p] * att[p], float4 vectorized
__global__ void mul_kernel(const float* __restrict__ img, float* __restrict__ out) {
    int i = blockIdx.x * blockDim.x + threadIdx.x;
    const int n4 = CIMG * HW / 4;
    if (i >= n4) return;
    float4 v = ((const float4*)img)[i];
    float4 a = ((const float4*)d_att)[i % (HW/4)];
    ((float4*)out)[i] = make_float4(v.x * a.x, v.y * a.y, v.z * a.z, v.w * a.w);
}

extern "C" void kernel_launch(void* const* d_in, const int* in_sizes, int n_in,
                              void* d_out, int out_size) {
    const float* img   = (const float*)d_in[0];
    const float* f0    = (const float*)d_in[1];
    const float* c0    = (const float*)d_in[2];
    const int*   g0    = (const int*)  d_in[3];
    const float* f1    = (const float*)d_in[4];
    const float* c1    = (const float*)d_in[5];
    const int*   g1    = (const int*)  d_in[6];
    const float* f2    = (const float*)d_in[7];
    const float* c2    = (const float*)d_in[8];
    const int*   g2    = (const int*)  d_in[9];
    const float* rd0_w = (const float*)d_in[10];
    const float* rd0_b = (const float*)d_in[11];
    const float* rd1_w = (const float*)d_in[12];
    const float* rd1_b = (const float*)d_in[13];
    const float* rd2_w = (const float*)d_in[14];
    const float* rd2_b = (const float*)d_in[15];
    const float* rd3_w = (const float*)d_in[16];
    const float* rd3_b = (const float*)d_in[17];
    const float* sp_w  = (const float*)d_in[18];
    const float* sp_b  = (const float*)d_in[19];

    int N0 = in_sizes[1] / 32;
    int N1 = in_sizes[4] / 64;
    int N2 = in_sizes[7] / 128;

    precompute_kernel<<<1, 512>>>(sp_w, rd0_w, rd1_w, rd0_b, rd1_b, rd2_w, rd2_b);
    zero_spt_kernel<<<(HW + 255) / 256, 256>>>();
    gated_kernel<<<(HW/4 + 255) / 256, 256>>>(img, rd3_w, rd3_b);
    scatter_kernel<32> <<<(N0 + 7) / 8, 256>>>(f0, c0, g0, N0);
    scatter_kernel<64> <<<(N1 + 7) / 8, 256>>>(f1, c1, g1, N1);
    scatter_kernel<128><<<(N2 + 7) / 8, 256>>>(f2, c2, g2, N2);
    att_kernel<<<(HW + 255) / 256, 256>>>(sp_b);
    mul_kernel<<<(CIMG * HW / 4 + 255) / 256, 256>>>(img, (float*)d_out);
}

// round 2
// speedup vs baseline: 1.1448x; 1.1448x over previous
#include <cuda_runtime.h>

#define Hh 256
#define Ww 704
#define HW (Hh*Ww)      // 180224 = 176*256*4
#define CIMG 256
#define COUTC 131

// Scratch (device globals; no allocation allowed)
__device__ float d_gated[HW];
__device__ float d_spt[HW];
__device__ float4 d_att4[HW/4];
__device__ float d_v2[9*COUTC];
__device__ float d_u0[9*35];
__device__ float d_u1[9*67];
__device__ float d_wg[9];
__device__ float d_K[9];

// ---------------------------------------------------------------------------
// Setup: block 0 folds weights; blocks 1..176 zero d_spt; 177..352 zero d_gated
// v2[t][j] = sum_c sp_w[c][t] * rd2_w[c][j]
// u0[t][i] = sum_j v2[t][j] * rd0_w[j][i]   (u1 analogous)
// wg[t]    = sum_c sp_w[c][t]
// K[t]     = sum_j v2[t][j]*(rd0_b[j]+rd1_b[j]) + sum_c sp_w[c][t]*rd2_b[c]
//            + wg[t]*rd3_b     (rd3_b folded here; d_gated is bias-free)
// ---------------------------------------------------------------------------
__global__ void setup_kernel(const float* __restrict__ sp_w,
                             const float* __restrict__ rd0_w,
                             const float* __restrict__ rd1_w,
                             const float* __restrict__ rd0_b,
                             const float* __restrict__ rd1_b,
                             const float* __restrict__ rd2_w,
                             const float* __restrict__ rd2_b,
                             const float* __restrict__ rd3_b) {
    int tid = threadIdx.x;
    if (blockIdx.x > 0) {
        int b = blockIdx.x - 1;
        float4* dst = (b < 176) ? (float4*)d_spt : (float4*)d_gated;
        int idx = (b % 176) * 256 + tid;
        dst[idx] = make_float4(0.f, 0.f, 0.f, 0.f);
        return;
    }
    for (int idx = tid; idx < 9*COUTC; idx += blockDim.x) {
        int t = idx / COUTC, j = idx % COUTC;
        float a = 0.f;
        for (int c = 0; c < COUTC; ++c) a += sp_w[c*9 + t] * rd2_w[c*COUTC + j];
        d_v2[idx] = a;
    }
    __syncthreads();
    for (int idx = tid; idx < 9*35; idx += blockDim.x) {
        int t = idx / 35, i = idx % 35;
        float a = 0.f;
        for (int j = 0; j < COUTC; ++j) a += d_v2[t*COUTC + j] * rd0_w[j*35 + i];
        d_u0[idx] = a;
    }
    for (int idx = tid; idx < 9*67; idx += blockDim.x) {
        int t = idx / 67, i = idx % 67;
        float a = 0.f;
        for (int j = 0; j < COUTC; ++j) a += d_v2[t*COUTC + j] * rd1_w[j*67 + i];
        d_u1[idx] = a;
    }
    if (tid < 9) {
        int t = tid;
        float w = 0.f, k = 0.f;
        for (int c = 0; c < COUTC; ++c) {
            w += sp_w[c*9 + t];
            k += d_v2[t*COUTC + c] * (rd0_b[c] + rd1_b[c]) + sp_w[c*9 + t] * rd2_b[c];
        }
        d_wg[t] = w;
        d_K[t]  = k + w * rd3_b[0];
    }
}

// ---------------------------------------------------------------------------
// gated(p) = sum_c rd3_w[c]*img[c][p], channel-split 4 ways, atomicAdd finish
// ---------------------------------------------------------------------------
__global__ void gated_kernel(const float* __restrict__ img,
                             const float* __restrict__ rd3_w) {
    __shared__ float sw[64];
    int c0 = blockIdx.y * 64;
    if (threadIdx.x < 64) sw[threadIdx.x] = rd3_w[c0 + threadIdx.x];
    __syncthreads();
    int p4 = blockIdx.x * 256 + threadIdx.x;
    const float4* img4 = (const float4*)img;
    float4 acc = make_float4(0.f, 0.f, 0.f, 0.f);
    #pragma unroll 16
    for (int c = 0; c < 64; ++c) {
        float w = sw[c];
        float4 x = __ldg(&img4[(size_t)(c0 + c) * (HW/4) + p4]);
        acc.x += w * x.x; acc.y += w * x.y; acc.z += w * x.z; acc.w += w * x.w;
    }
    atomicAdd(&d_gated[4*p4 + 0], acc.x);
    atomicAdd(&d_gated[4*p4 + 1], acc.y);
    atomicAdd(&d_gated[4*p4 + 2], acc.z);
    atomicAdd(&d_gated[4*p4 + 3], acc.w);
}

// ---------------------------------------------------------------------------
// Scatter: warp = 3 points x 9 taps. Each lane computes one tap's dot product
// (float4 over features + 3 coord scalars) and atomicAdds to its neighbor pixel.
// No shuffles, no reductions.
// ---------------------------------------------------------------------------
template<int CF>
__device__ __forceinline__ void scatter_level(const float* __restrict__ feat,
                                              const float* __restrict__ coord,
                                              const int* __restrict__ grid,
                                              int N, const float* __restrict__ u,
                                              int blockInLevel, int blocksInLevel) {
    constexpr int L  = CF + 3;
    constexpr int LP = CF + 4;                    // padded row, mult of 4
    __shared__ __align__(16) float su[9 * LP];
    for (int idx = threadIdx.x; idx < 9 * L; idx += blockDim.x) {
        int t = idx / L, i = idx - t * L;
        su[t * LP + i] = u[idx];
    }
    __syncthreads();
    int warpsPerBlock = blockDim.x >> 5;
    int warpInLevel = blockInLevel * warpsPerBlock + (threadIdx.x >> 5);
    int nwarps = blocksInLevel * warpsPerBlock;
    int lane = threadIdx.x & 31;
    int g = lane / 9;                              // point-in-group 0..2 (3 if idle)
    int t = lane - g * 9;                          // tap 0..8
    bool laneActive = lane < 27;
    const float* surow = &su[t * LP];
    for (int base = warpInLevel * 3; base < N; base += nwarps * 3) {
        int n = base + g;
        if (laneActive && n < N) {
            const float4* fp = (const float4*)(feat + (size_t)n * CF);
            float4 a = make_float4(0.f, 0.f, 0.f, 0.f);
            #pragma unroll
            for (int j = 0; j < CF / 4; ++j) {
                float4 p = __ldg(fp + j);
                float4 w = *(const float4*)(surow + 4 * j);
                a.x += w.x * p.x; a.y += w.y * p.y;
                a.z += w.z * p.z; a.w += w.w * p.w;
            }
            float ac = (a.x + a.y) + (a.z + a.w);
            ac += surow[CF + 0] * __ldg(coord + n * 3 + 0);
            ac += surow[CF + 1] * __ldg(coord + n * 3 + 1);
            ac += surow[CF + 2] * __ldg(coord + n * 3 + 2);
            int2 gxy = __ldg((const int2*)grid + n);       // (col, row)
            int h = gxy.y - t / 3 + 1;
            int w = gxy.x - t % 3 + 1;
            if (h >= 0 && h < Hh && w >= 0 && w < Ww)
                atomicAdd(&d_spt[h * Ww + w], ac);
        }
    }
}

#define B0 280
#define B1 430
#define B2 630

__global__ void scatter_all_kernel(const float* __restrict__ f0, const float* __restrict__ c0,
                                   const int* __restrict__ g0, int N0,
                                   const float* __restrict__ f1, const float* __restrict__ c1,
                                   const int* __restrict__ g1, int N1,
                                   const float* __restrict__ f2, const float* __restrict__ c2,
                                   const int* __restrict__ g2, int N2) {
    int b = blockIdx.x;
    if (b < B0) {
        scatter_level<32>(f0, c0, g0, N0, d_u0, b, B0);
    } else if (b < B0 + B1) {
        scatter_level<64>(f1, c1, g1, N1, d_u1, b - B0, B1);
    } else {
        scatter_level<128>(f2, c2, g2, N2, d_v2, b - B0 - B1, B2);
    }
}

// ---------------------------------------------------------------------------
// att(p) = sigmoid( sp_b + spt(p) + sum_{in-bounds taps} (wg_t*gated(nbr) + K_t) )
// ---------------------------------------------------------------------------
__global__ void att_kernel(const float* __restrict__ sp_b) {
    int p = blockIdx.x * blockDim.x + threadIdx.x;
    if (p >= HW) return;
    int h = p / Ww, w = p - h * Ww;
    float s = sp_b[0] + d_spt[p];
    #pragma unroll
    for (int t = 0; t < 9; ++t) {
        int y = h + t / 3 - 1, x = w + t % 3 - 1;
        if (y >= 0 && y < Hh && x >= 0 && x < Ww)
            s += d_wg[t] * d_gated[y * Ww + x] + d_K[t];
    }
    ((float*)d_att4)[p] = 1.f / (1.f + __expf(-s));
}

// ---------------------------------------------------------------------------
// out[c][p] = img[c][p] * att[p]; grid (176, 8), 32 channels per block
// ---------------------------------------------------------------------------
__global__ void mul_kernel(const float* __restrict__ img, float* __restrict__ out) {
    int p4 = blockIdx.x * 256 + threadIdx.x;
    float4 a = __ldg(&d_att4[p4]);
    size_t off = (size_t)blockIdx.y * 32 * (HW/4) + p4;
    const float4* img4 = (const float4*)img;
    float4* out4 = (float4*)out;
    #pragma unroll 8
    for (int c = 0; c < 32; ++c) {
        float4 v = __ldg(&img4[off + (size_t)c * (HW/4)]);
        out4[off + (size_t)c * (HW/4)] =
            make_float4(v.x * a.x, v.y * a.y, v.z * a.z, v.w * a.w);
    }
}

extern "C" void kernel_launch(void* const* d_in, const int* in_sizes, int n_in,
                              void* d_out, int out_size) {
    const float* img   = (const float*)d_in[0];
    const float* f0    = (const float*)d_in[1];
    const float* c0    = (const float*)d_in[2];
    const int*   g0    = (const int*)  d_in[3];
    const float* f1    = (const float*)d_in[4];
    const float* c1    = (const float*)d_in[5];
    const int*   g1    = (const int*)  d_in[6];
    const float* f2    = (const float*)d_in[7];
    const float* c2    = (const float*)d_in[8];
    const int*   g2    = (const int*)  d_in[9];
    const float* rd0_w = (const float*)d_in[10];
    const float* rd0_b = (const float*)d_in[11];
    const float* rd1_w = (const float*)d_in[12];
    const float* rd1_b = (const float*)d_in[13];
    const float* rd2_w = (const float*)d_in[14];
    const float* rd2_b = (const float*)d_in[15];
    const float* rd3_w = (const float*)d_in[16];
    const float* rd3_b = (const float*)d_in[17];
    const float* sp_w  = (const float*)d_in[18];
    const float* sp_b  = (const float*)d_in[19];

    int N0 = in_sizes[1] / 32;
    int N1 = in_sizes[4] / 64;
    int N2 = in_sizes[7] / 128;

    setup_kernel<<<353, 256>>>(sp_w, rd0_w, rd1_w, rd0_b, rd1_b, rd2_w, rd2_b, rd3_b);
    gated_kernel<<<dim3(176, 4), 256>>>(img, rd3_w);
    scatter_all_kernel<<<B0 + B1 + B2, 256>>>(f0, c0, g0, N0,
                                              f1, c1, g1, N1,
                                              f2, c2, g2, N2);
    att_kernel<<<HW / 256, 256>>>(sp_b);
    mul_kernel<<<dim3(176, 8), 256>>>(img, (float*)d_out);
}

// round 3
// speedup vs baseline: 1.1645x; 1.0172x over previous
#include <cuda_runtime.h>

#define Hh 256
#define Ww 704
#define HW (Hh*Ww)      // 180224 = 176*256*4
#define CIMG 256
#define COUTC 131

// Scratch (device globals; no allocation allowed)
__device__ float d_gated[HW];
__device__ float d_spt[HW];
__device__ float4 d_att4[HW/4];
__device__ float d_v2[9*COUTC];
__device__ float d_u0[9*35];
__device__ float d_u1[9*67];
__device__ float d_wg[9];
__device__ float d_K[9];

// ---------------------------------------------------------------------------
// Setup: block 0 folds weights; blocks 1..176 zero d_spt; 177..352 zero d_gated
// ---------------------------------------------------------------------------
__global__ void setup_kernel(const float* __restrict__ sp_w,
                             const float* __restrict__ rd0_w,
                             const float* __restrict__ rd1_w,
                             const float* __restrict__ rd0_b,
                             const float* __restrict__ rd1_b,
                             const float* __restrict__ rd2_w,
                             const float* __restrict__ rd2_b,
                             const float* __restrict__ rd3_b) {
    int tid = threadIdx.x;
    if (blockIdx.x > 0) {
        int b = blockIdx.x - 1;
        float4* dst = (b < 176) ? (float4*)d_spt : (float4*)d_gated;
        int idx = (b % 176) * 256 + tid;
        dst[idx] = make_float4(0.f, 0.f, 0.f, 0.f);
        return;
    }
    for (int idx = tid; idx < 9*COUTC; idx += blockDim.x) {
        int t = idx / COUTC, j = idx % COUTC;
        float a = 0.f;
        for (int c = 0; c < COUTC; ++c) a += sp_w[c*9 + t] * rd2_w[c*COUTC + j];
        d_v2[idx] = a;
    }
    __syncthreads();
    for (int idx = tid; idx < 9*35; idx += blockDim.x) {
        int t = idx / 35, i = idx % 35;
        float a = 0.f;
        for (int j = 0; j < COUTC; ++j) a += d_v2[t*COUTC + j] * rd0_w[j*35 + i];
        d_u0[idx] = a;
    }
    for (int idx = tid; idx < 9*67; idx += blockDim.x) {
        int t = idx / 67, i = idx % 67;
        float a = 0.f;
        for (int j = 0; j < COUTC; ++j) a += d_v2[t*COUTC + j] * rd1_w[j*67 + i];
        d_u1[idx] = a;
    }
    if (tid < 9) {
        int t = tid;
        float w = 0.f, k = 0.f;
        for (int c = 0; c < COUTC; ++c) {
            w += sp_w[c*9 + t];
            k += d_v2[t*COUTC + c] * (rd0_b[c] + rd1_b[c]) + sp_w[c*9 + t] * rd2_b[c];
        }
        d_wg[t] = w;
        d_K[t]  = k + w * rd3_b[0];
    }
}

// ---------------------------------------------------------------------------
// Gated part: 704 blocks (176 pixel-groups x 4 channel-quarters), atomic finish
// ---------------------------------------------------------------------------
__device__ __forceinline__ void gated_part(const float* __restrict__ img,
                                           const float* __restrict__ rd3_w,
                                           int b) {
    __shared__ float sw[64];
    int pb = b % 176, cb = b / 176;
    int c0 = cb * 64;
    if (threadIdx.x < 64) sw[threadIdx.x] = rd3_w[c0 + threadIdx.x];
    __syncthreads();
    int p4 = pb * 256 + threadIdx.x;
    const float4* img4 = (const float4*)img;
    float4 acc = make_float4(0.f, 0.f, 0.f, 0.f);
    #pragma unroll 16
    for (int c = 0; c < 64; ++c) {
        float w = sw[c];
        float4 x = __ldcs(&img4[(size_t)(c0 + c) * (HW/4) + p4]);
        acc.x += w * x.x; acc.y += w * x.y; acc.z += w * x.z; acc.w += w * x.w;
    }
    atomicAdd(&d_gated[4*p4 + 0], acc.x);
    atomicAdd(&d_gated[4*p4 + 1], acc.y);
    atomicAdd(&d_gated[4*p4 + 2], acc.z);
    atomicAdd(&d_gated[4*p4 + 3], acc.w);
}

// ---------------------------------------------------------------------------
// Scatter: warp = 3 points x 9 taps; per-lane dot product + one atomicAdd.
// ---------------------------------------------------------------------------
template<int CF>
__device__ __forceinline__ void scatter_level(const float* __restrict__ feat,
                                              const float* __restrict__ coord,
                                              const int* __restrict__ grid,
                                              int N, const float* __restrict__ u,
                                              int blockInLevel, int blocksInLevel) {
    constexpr int L  = CF + 3;
    constexpr int LP = CF + 4;                    // padded row, mult of 4
    __shared__ __align__(16) float su[9 * LP];
    for (int idx = threadIdx.x; idx < 9 * L; idx += blockDim.x) {
        int t = idx / L, i = idx - t * L;
        su[t * LP + i] = u[idx];
    }
    __syncthreads();
    int warpsPerBlock = blockDim.x >> 5;
    int warpInLevel = blockInLevel * warpsPerBlock + (threadIdx.x >> 5);
    int nwarps = blocksInLevel * warpsPerBlock;
    int lane = threadIdx.x & 31;
    int g = lane / 9;                              // point-in-group 0..2 (3 if idle)
    int t = lane - g * 9;                          // tap 0..8
    bool laneActive = lane < 27;
    const float* surow = &su[t * LP];
    for (int base = warpInLevel * 3; base < N; base += nwarps * 3) {
        int n = base + g;
        if (laneActive && n < N) {
            const float4* fp = (const float4*)(feat + (size_t)n * CF);
            float4 a = make_float4(0.f, 0.f, 0.f, 0.f);
            #pragma unroll
            for (int j = 0; j < CF / 4; ++j) {
                float4 p = __ldg(fp + j);
                float4 w = *(const float4*)(surow + 4 * j);
                a.x += w.x * p.x; a.y += w.y * p.y;
                a.z += w.z * p.z; a.w += w.w * p.w;
            }
            float ac = (a.x + a.y) + (a.z + a.w);
            ac += surow[CF + 0] * __ldg(coord + n * 3 + 0);
            ac += surow[CF + 1] * __ldg(coord + n * 3 + 1);
            ac += surow[CF + 2] * __ldg(coord + n * 3 + 2);
            int2 gxy = __ldg((const int2*)grid + n);       // (col, row)
            int h = gxy.y - t / 3 + 1;
            int w = gxy.x - t % 3 + 1;
            if (h >= 0 && h < Hh && w >= 0 && w < Ww)
                atomicAdd(&d_spt[h * Ww + w], ac);
        }
    }
}

#define B0 280
#define B1 430
#define B2 630
#define GB 704   // gated blocks

// Combined gated + scatter: independent work, one launch, runs concurrently.
__global__ void work_kernel(const float* __restrict__ img, const float* __restrict__ rd3_w,
                            const float* __restrict__ f0, const float* __restrict__ c0,
                            const int* __restrict__ g0, int N0,
                            const float* __restrict__ f1, const float* __restrict__ c1,
                            const int* __restrict__ g1, int N1,
                            const float* __restrict__ f2, const float* __restrict__ c2,
                            const int* __restrict__ g2, int N2) {
    int b = blockIdx.x;
    if (b < GB) {
        gated_part(img, rd3_w, b);
    } else if (b < GB + B0) {
        scatter_level<32>(f0, c0, g0, N0, d_u0, b - GB, B0);
    } else if (b < GB + B0 + B1) {
        scatter_level<64>(f1, c1, g1, N1, d_u1, b - GB - B0, B1);
    } else {
        scatter_level<128>(f2, c2, g2, N2, d_v2, b - GB - B0 - B1, B2);
    }
}

// ---------------------------------------------------------------------------
// att(p) = sigmoid( sp_b + spt(p) + sum_{in-bounds taps} (wg_t*gated(nbr) + K_t) )
// ---------------------------------------------------------------------------
__global__ void att_kernel(const float* __restrict__ sp_b) {
    int p = blockIdx.x * blockDim.x + threadIdx.x;
    if (p >= HW) return;
    int h = p / Ww, w = p - h * Ww;
    float s = sp_b[0] + d_spt[p];
    #pragma unroll
    for (int t = 0; t < 9; ++t) {
        int y = h + t / 3 - 1, x = w + t % 3 - 1;
        if (y >= 0 && y < Hh && x >= 0 && x < Ww)
            s += d_wg[t] * d_gated[y * Ww + x] + d_K[t];
    }
    ((float*)d_att4)[p] = 1.f / (1.f + __expf(-s));
}

// ---------------------------------------------------------------------------
// out[c][p] = img[c][p] * att[p]; grid (176, 8), 32 channels per block.
// img/out are streamed (.cs) — no L2 reuse possible (184MB each).
// ---------------------------------------------------------------------------
__global__ void mul_kernel(const float* __restrict__ img, float* __restrict__ out) {
    int p4 = blockIdx.x * 256 + threadIdx.x;
    float4 a = __ldg(&d_att4[p4]);
    size_t off = (size_t)blockIdx.y * 32 * (HW/4) + p4;
    const float4* img4 = (const float4*)img;
    float4* out4 = (float4*)out;
    #pragma unroll 8
    for (int c = 0; c < 32; ++c) {
        float4 v = __ldcs(&img4[off + (size_t)c * (HW/4)]);
        float4 r = make_float4(v.x * a.x, v.y * a.y, v.z * a.z, v.w * a.w);
        __stcs(&out4[off + (size_t)c * (HW/4)], r);
    }
}

extern "C" void kernel_launch(void* const* d_in, const int* in_sizes, int n_in,
                              void* d_out, int out_size) {
    const float* img   = (const float*)d_in[0];
    const float* f0    = (const float*)d_in[1];
    const float* c0    = (const float*)d_in[2];
    const int*   g0    = (const int*)  d_in[3];
    const float* f1    = (const float*)d_in[4];
    const float* c1    = (const float*)d_in[5];
    const int*   g1    = (const int*)  d_in[6];
    const float* f2    = (const float*)d_in[7];
    const float* c2    = (const float*)d_in[8];
    const int*   g2    = (const int*)  d_in[9];
    const float* rd0_w = (const float*)d_in[10];
    const float* rd0_b = (const float*)d_in[11];
    const float* rd1_w = (const float*)d_in[12];
    const float* rd1_b = (const float*)d_in[13];
    const float* rd2_w = (const float*)d_in[14];
    const float* rd2_b = (const float*)d_in[15];
    const float* rd3_w = (const float*)d_in[16];
    const float* rd3_b = (const float*)d_in[17];
    const float* sp_w  = (const float*)d_in[18];
    const float* sp_b  = (const float*)d_in[19];

    int N0 = in_sizes[1] / 32;
    int N1 = in_sizes[4] / 64;
    int N2 = in_sizes[7] / 128;

    setup_kernel<<<353, 256>>>(sp_w, rd0_w, rd1_w, rd0_b, rd1_b, rd2_w, rd2_b, rd3_b);
    work_kernel<<<GB + B0 + B1 + B2, 256>>>(img, rd3_w,
                                            f0, c0, g0, N0,
                                            f1, c1, g1, N1,
                                            f2, c2, g2, N2);
    att_kernel<<<HW / 256, 256>>>(sp_b);
    mul_kernel<<<dim3(176, 8), 256>>>(img, (float*)d_out);
}